// round 1
// baseline (speedup 1.0000x reference)
#include <cuda_runtime.h>
#include <cstdint>

// SDPA causal GQA flash-attention, tf32 mma.sync baseline.
// Shapes (fixed by problem): S=2048, H=32, HKV=8, D=128.
// input_pos == arange(S) and the causal mask make cache/mask inputs dead:
// this is exactly causal attention over q/k/v with kv-head = h/4.

#define S_LEN 2048
#define NH 32
#define NKV 8
#define HD 128
#define BM 128
#define BN 64
#define QSTRIDE 132
#define KSTRIDE 132
#define VSTRIDE 136
#define PSTRIDE 68

// floats of smem
#define SMEM_FLOATS (BM*QSTRIDE + BN*KSTRIDE + BN*VSTRIDE + BM*PSTRIDE)
#define SMEM_BYTES (SMEM_FLOATS * 4)

__device__ __forceinline__ uint32_t f2tf32(float x) {
    uint32_t r;
    asm("cvt.rna.tf32.f32 %0, %1;" : "=r"(r) : "f"(x));
    return r;
}

__device__ __forceinline__ void mma_tf32(float c[4],
                                         uint32_t a0, uint32_t a1, uint32_t a2, uint32_t a3,
                                         uint32_t b0, uint32_t b1) {
    asm volatile(
        "mma.sync.aligned.m16n8k8.row.col.f32.tf32.tf32.f32 "
        "{%0,%1,%2,%3}, {%4,%5,%6,%7}, {%8,%9}, {%0,%1,%2,%3};\n"
        : "+f"(c[0]), "+f"(c[1]), "+f"(c[2]), "+f"(c[3])
        : "r"(a0), "r"(a1), "r"(a2), "r"(a3), "r"(b0), "r"(b1));
}

__global__ __launch_bounds__(256, 1)
void sdpa_fa_tf32_kernel(const float* __restrict__ q,
                         const float* __restrict__ k,
                         const float* __restrict__ v,
                         float* __restrict__ out) {
    extern __shared__ float sm[];
    float* Qs = sm;                         // [BM][QSTRIDE]
    float* Ks = Qs + BM * QSTRIDE;          // [BN][KSTRIDE]
    float* Vs = Ks + BN * KSTRIDE;          // [BN][VSTRIDE]
    float* Ps = Vs + BN * VSTRIDE;          // [BM][PSTRIDE]

    const int tid  = threadIdx.x;
    const int warp = tid >> 5;
    const int lane = tid & 31;
    const int gp   = lane >> 2;   // 0..7
    const int tg   = lane & 3;    // 0..3
    // heaviest (most KV tiles) query blocks first
    const int qb = (int)gridDim.x - 1 - (int)blockIdx.x;
    const int h  = blockIdx.y;
    const int hk = h >> 2;        // repeat_interleave: q head h -> kv head h/4
    const int q0 = qb * BM;

    const float SCALE = 0.08838834764831845f;  // 1/sqrt(128)
    const float L2E   = 1.44269504088896f;

    // ---- load Q tile, scale + round-to-tf32 ----
    for (int i = tid; i < BM * (HD / 4); i += 256) {
        int r = i >> 5;
        int c = (i & 31) << 2;
        const float4 qv = *reinterpret_cast<const float4*>(
            &q[((size_t)(q0 + r) * NH + h) * HD + c]);
        float* dst = &Qs[r * QSTRIDE + c];
        dst[0] = __uint_as_float(f2tf32(qv.x * SCALE));
        dst[1] = __uint_as_float(f2tf32(qv.y * SCALE));
        dst[2] = __uint_as_float(f2tf32(qv.z * SCALE));
        dst[3] = __uint_as_float(f2tf32(qv.w * SCALE));
    }

    float o[16][4];
    #pragma unroll
    for (int n = 0; n < 16; ++n) {
        o[n][0] = 0.f; o[n][1] = 0.f; o[n][2] = 0.f; o[n][3] = 0.f;
    }
    float mrow[2] = {-1e30f, -1e30f};
    float lrow[2] = {0.f, 0.f};

    const int ntiles = 2 * qb + 2;  // causal: keys up to q0+BM-1
    for (int kt = 0; kt < ntiles; ++kt) {
        __syncthreads();  // Qs ready (iter0) / Ks,Vs consumers done (iter>0)

        // ---- load K,V tile (tf32-rounded) ----
        for (int i = tid; i < BN * (HD / 4); i += 256) {
            int r = i >> 5;
            int c = (i & 31) << 2;
            size_t gidx = ((size_t)(kt * BN + r) * NKV + hk) * HD + c;
            float4 kv = *reinterpret_cast<const float4*>(&k[gidx]);
            float* kd = &Ks[r * KSTRIDE + c];
            kd[0] = __uint_as_float(f2tf32(kv.x));
            kd[1] = __uint_as_float(f2tf32(kv.y));
            kd[2] = __uint_as_float(f2tf32(kv.z));
            kd[3] = __uint_as_float(f2tf32(kv.w));
            float4 vv = *reinterpret_cast<const float4*>(&v[gidx]);
            float* vd = &Vs[r * VSTRIDE + c];
            vd[0] = __uint_as_float(f2tf32(vv.x));
            vd[1] = __uint_as_float(f2tf32(vv.y));
            vd[2] = __uint_as_float(f2tf32(vv.z));
            vd[3] = __uint_as_float(f2tf32(vv.w));
        }
        __syncthreads();

        // ---- S = Q K^T  (8 n-tiles of 8 keys, 16 k-steps over D) ----
        float s[8][4];
        #pragma unroll
        for (int n = 0; n < 8; ++n) {
            s[n][0] = 0.f; s[n][1] = 0.f; s[n][2] = 0.f; s[n][3] = 0.f;
        }
        const float* qbase = &Qs[(warp * 16 + gp) * QSTRIDE + tg];
        const float* kbase = &Ks[gp * KSTRIDE + tg];
        #pragma unroll 4
        for (int kk = 0; kk < 16; ++kk) {
            uint32_t a0 = __float_as_uint(qbase[kk * 8]);
            uint32_t a1 = __float_as_uint(qbase[8 * QSTRIDE + kk * 8]);
            uint32_t a2 = __float_as_uint(qbase[kk * 8 + 4]);
            uint32_t a3 = __float_as_uint(qbase[8 * QSTRIDE + kk * 8 + 4]);
            #pragma unroll
            for (int n = 0; n < 8; ++n) {
                uint32_t b0 = __float_as_uint(kbase[n * 8 * KSTRIDE + kk * 8]);
                uint32_t b1 = __float_as_uint(kbase[n * 8 * KSTRIDE + kk * 8 + 4]);
                mma_tf32(s[n], a0, a1, a2, a3, b0, b1);
            }
        }

        // ---- causal mask (only the top two tiles can cross the diagonal) ----
        if (kt >= 2 * qb) {
            const int key0  = kt * BN + tg * 2;
            const int qrow0 = q0 + warp * 16 + gp;
            #pragma unroll
            for (int n = 0; n < 8; ++n) {
                int kc = key0 + n * 8;
                if (kc     > qrow0)     s[n][0] = -1e30f;
                if (kc + 1 > qrow0)     s[n][1] = -1e30f;
                if (kc     > qrow0 + 8) s[n][2] = -1e30f;
                if (kc + 1 > qrow0 + 8) s[n][3] = -1e30f;
            }
        }

        // ---- online softmax (2 rows per thread: gp and gp+8 of warp's 16) ----
        #pragma unroll
        for (int r = 0; r < 2; ++r) {
            float mx = -1e30f;
            #pragma unroll
            for (int n = 0; n < 8; ++n)
                mx = fmaxf(mx, fmaxf(s[n][2 * r], s[n][2 * r + 1]));
            mx = fmaxf(mx, __shfl_xor_sync(0xffffffff, mx, 1));
            mx = fmaxf(mx, __shfl_xor_sync(0xffffffff, mx, 2));
            float mnew  = fmaxf(mrow[r], mx);
            float alpha = exp2f((mrow[r] - mnew) * L2E);
            mrow[r] = mnew;
            float sum = 0.f;
            float* prow = &Ps[(warp * 16 + gp + r * 8) * PSTRIDE + tg * 2];
            #pragma unroll
            for (int n = 0; n < 8; ++n) {
                float p0 = exp2f((s[n][2 * r]     - mnew) * L2E);
                float p1 = exp2f((s[n][2 * r + 1] - mnew) * L2E);
                sum += p0 + p1;
                prow[n * 8]     = __uint_as_float(f2tf32(p0));
                prow[n * 8 + 1] = __uint_as_float(f2tf32(p1));
            }
            sum += __shfl_xor_sync(0xffffffff, sum, 1);
            sum += __shfl_xor_sync(0xffffffff, sum, 2);
            lrow[r] = lrow[r] * alpha + sum;
            #pragma unroll
            for (int n = 0; n < 16; ++n) {
                o[n][2 * r]     *= alpha;
                o[n][2 * r + 1] *= alpha;
            }
        }
        __syncwarp();  // Ps is warp-private; make writes visible for A-frag reads

        // ---- O += P V  (16 n-tiles over D, 8 k-steps over BN) ----
        const float* pbase = &Ps[(warp * 16 + gp) * PSTRIDE + tg];
        const float* vbase = &Vs[tg * VSTRIDE + gp];
        #pragma unroll 2
        for (int kk = 0; kk < 8; ++kk) {
            uint32_t a0 = __float_as_uint(pbase[kk * 8]);
            uint32_t a1 = __float_as_uint(pbase[8 * PSTRIDE + kk * 8]);
            uint32_t a2 = __float_as_uint(pbase[kk * 8 + 4]);
            uint32_t a3 = __float_as_uint(pbase[8 * PSTRIDE + kk * 8 + 4]);
            #pragma unroll
            for (int n = 0; n < 16; ++n) {
                uint32_t b0 = __float_as_uint(vbase[kk * 8 * VSTRIDE + n * 8]);
                uint32_t b1 = __float_as_uint(vbase[(kk * 8 + 4) * VSTRIDE + n * 8]);
                mma_tf32(o[n], a0, a1, a2, a3, b0, b1);
            }
        }
    }

    // ---- epilogue: O / l, write [s, h, d] ----
    #pragma unroll
    for (int r = 0; r < 2; ++r) {
        float inv = 1.f / lrow[r];
        int row = q0 + warp * 16 + gp + r * 8;
        float* obase = &out[((size_t)row * NH + h) * HD + tg * 2];
        #pragma unroll
        for (int n = 0; n < 16; ++n) {
            float2 val = make_float2(o[n][2 * r] * inv, o[n][2 * r + 1] * inv);
            *reinterpret_cast<float2*>(&obase[n * 8]) = val;
        }
    }
}

extern "C" void kernel_launch(void* const* d_in, const int* in_sizes, int n_in,
                              void* d_out, int out_size) {
    // Identify q/k/v by element count (robust to scalar inputs in the list):
    // q: 2048*32*128 = 8388608 ; k,v: 2048*8*128 = 2097152 (k before v).
    const float* q = nullptr;
    const float* k = nullptr;
    const float* v = nullptr;
    int kv_seen = 0;
    for (int i = 0; i < n_in; ++i) {
        int sz = in_sizes[i];
        if (sz == S_LEN * NH * HD) {
            q = (const float*)d_in[i];
        } else if (sz == S_LEN * NKV * HD) {
            if (kv_seen++ == 0) k = (const float*)d_in[i];
            else                v = (const float*)d_in[i];
        }
    }

    cudaFuncSetAttribute(sdpa_fa_tf32_kernel,
                         cudaFuncAttributeMaxDynamicSharedMemorySize, SMEM_BYTES);

    dim3 grid(S_LEN / BM, NH);
    sdpa_fa_tf32_kernel<<<grid, 256, SMEM_BYTES>>>(q, k, v, (float*)d_out);
}